// round 7
// baseline (speedup 1.0000x reference)
#include <cuda_runtime.h>
#include <cuda_bf16.h>
#include <cstdint>

#define BB 8
#define NN 2048
#define DD 64
#define TIM 64               // i-rows per CTA (4 warps x 16)
#define KC 64                // j-chunk
#define SPLIT 4
#define CPS (NN / KC / SPLIT)   // 8 chunks per split
#define PITCH 144            // smem H row pitch (bytes): conflict-free ldmatrix

// ---- device scratch ----
__device__ __nv_bfloat16 g_hb[BB * NN * DD];  // H: [n][d] bf16
__device__ float g_s[BB * NN];                // exp(a_src)
__device__ float g_t[BB * NN];                // exp(a_dst)
__device__ float g_u[BB * NN];                // exp(0.2*a_src)
__device__ float g_v[BB * NN];                // exp(0.2*a_dst)
__device__ float g_lam[2 * DD];               // lambda_adj[64], lambda_job[64]
// split-K partials
__device__ float g_nA[SPLIT][BB * NN * DD];
__device__ float g_nJ[SPLIT][BB * NN * DD];
__device__ float g_dA[SPLIT][BB * NN];
__device__ float g_dJ[SPLIT][BB * NN];

// ---- PTX helpers (base-target instructions only: sm_80/75) ----
__device__ __forceinline__ void mma_bf16(float* d,
    uint32_t a0, uint32_t a1, uint32_t a2, uint32_t a3, uint32_t b0, uint32_t b1) {
    asm volatile(
        "mma.sync.aligned.m16n8k16.row.col.f32.bf16.bf16.f32 "
        "{%0,%1,%2,%3}, {%4,%5,%6,%7}, {%8,%9}, {%0,%1,%2,%3};"
        : "+f"(d[0]), "+f"(d[1]), "+f"(d[2]), "+f"(d[3])
        : "r"(a0), "r"(a1), "r"(a2), "r"(a3), "r"(b0), "r"(b1));
}
__device__ __forceinline__ void ldsm4t(uint32_t& r0, uint32_t& r1, uint32_t& r2, uint32_t& r3, uint32_t addr) {
    asm volatile("ldmatrix.sync.aligned.m8n8.x4.trans.shared.b16 {%0,%1,%2,%3}, [%4];"
        : "=r"(r0), "=r"(r1), "=r"(r2), "=r"(r3) : "r"(addr));
}
__device__ __forceinline__ uint32_t packbf(float lo, float hi) {
    uint32_t r;
    asm("cvt.rn.satfinite.bf16x2.f32 %0, %1, %2;" : "=r"(r) : "f"(hi), "f"(lo));
    return r;
}
#define CP16(dst, src) asm volatile("cp.async.cg.shared.global [%0], [%1], 16;" :: "r"(dst), "l"(src))
#define CP_COMMIT()    asm volatile("cp.async.commit_group;" ::: "memory")
#define CP_WAIT0()     asm volatile("cp.async.wait_group 0;" ::: "memory")

__device__ __forceinline__ float pvsel(float st, float uv) { return (st >= 1.0f) ? st : uv; }

// =====================================================================
// Kernel A: h = feats @ W^T (bf16), exps, lambdas.
// 512 threads = 16 warps; warp = one row; lane computes 2 outputs.
// grid = B*N/16
// =====================================================================
__global__ __launch_bounds__(512) void prep_kernel(
    const float* __restrict__ feats, const float* __restrict__ W,
    const float* __restrict__ attn_src, const float* __restrict__ attn_dst,
    const float* __restrict__ lambda_params)
{
    __shared__ float sWt[DD * 66];   // sWt[d*66+o] = W[o][d], pairs 8B-aligned
    __shared__ float sF[16][DD];

    const int t = threadIdx.x;
    const int warp = t >> 5, lane = t & 31;
    const int o = lane * 2;
    const int row = blockIdx.x * 16 + warp;

    #pragma unroll
    for (int w = 0; w < 8; ++w) {
        int x = t + 512 * w;
        sWt[(x & 63) * 66 + (x >> 6)] = W[x];
    }
    *(float2*)&sF[warp][o] = *(const float2*)(feats + (size_t)row * DD + o);
    __syncthreads();

    float h0 = 0.f, h1 = 0.f;
    #pragma unroll
    for (int d = 0; d < DD; ++d) {
        const float fd = sF[warp][d];
        const float2 w2 = *(const float2*)&sWt[d * 66 + o];
        h0 = fmaf(fd, w2.x, h0);
        h1 = fmaf(fd, w2.y, h1);
    }

    *(__nv_bfloat162*)(g_hb + (size_t)row * DD + o) =
        __nv_bfloat162(__float2bfloat16(h0), __float2bfloat16(h1));

    const float2 ws = *(const float2*)(attn_src + o);
    const float2 wd = *(const float2*)(attn_dst + o);
    float rs = h0 * ws.x + h1 * ws.y;
    float rd = h0 * wd.x + h1 * wd.y;
    #pragma unroll
    for (int off = 16; off; off >>= 1) {
        rs += __shfl_down_sync(0xffffffffu, rs, off);
        rd += __shfl_down_sync(0xffffffffu, rd, off);
    }
    if (lane == 0) {
        g_s[row] = expf(rs);
        g_u[row] = expf(0.2f * rs);
        g_t[row] = expf(rd);
        g_v[row] = expf(0.2f * rd);
    }
    if (blockIdx.x == 0 && t >= 64 && t < 128) {
        int d = t - 64;
        float l0 = lambda_params[d * 2];
        float l1 = lambda_params[d * 2 + 1];
        float m = fmaxf(l0, l1);
        float e0 = expf(l0 - m), e1 = expf(l1 - m);
        float inv = 1.0f / (e0 + e1);
        g_lam[d] = e0 * inv;
        g_lam[DD + d] = e1 * inv;
    }
}

// =====================================================================
// Kernel B: HMMA dual-masked attention, split-K over j
// grid = (NN/TIM=32, BB=8, SPLIT=4), 128 threads (4 warps x 16 rows)
// =====================================================================
__global__ __launch_bounds__(128, 3) void attn_hmma_kernel(
    const int* __restrict__ mask_adj, const int* __restrict__ mask_job,
    const int* __restrict__ bidx)
{
    __shared__ __align__(16) char  sH[2][KC * PITCH];
    __shared__ __align__(16) float sT[2][KC], sV[2][KC];

    const int t = threadIdx.x;
    const int lane = t & 31, wid = t >> 5;
    const int b = blockIdx.y;
    const int sp = blockIdx.z;
    const int i_base = blockIdx.x * TIM;
    const int bN = b * NN;

    int mb = bidx[b];                 // arange(B) identity gather; clamp defensively
    if (mb < 0 || mb >= BB) mb = b;

    const int g  = lane >> 2;
    const int tq = lane & 3;
    const int r0 = wid * 16 + g;
    const int r1 = r0 + 8;

    const float si0 = g_s[bN + i_base + r0], ui0 = g_u[bN + i_base + r0];
    const float si1 = g_s[bN + i_base + r1], ui1 = g_u[bN + i_base + r1];

    const int* pa0 = mask_adj + ((size_t)mb * NN + i_base + r0) * NN;
    const int* pa1 = pa0 + (size_t)8 * NN;
    const int* pj0 = mask_job + ((size_t)mb * NN + i_base + r0) * NN;
    const int* pj1 = pj0 + (size_t)8 * NN;

    const uint32_t shb0 = (uint32_t)__cvta_generic_to_shared(&sH[0][0]);
    const uint32_t shb1 = (uint32_t)__cvta_generic_to_shared(&sH[1][0]);
    const uint32_t stb0 = (uint32_t)__cvta_generic_to_shared(&sT[0][0]);
    const uint32_t stb1 = (uint32_t)__cvta_generic_to_shared(&sT[1][0]);
    const uint32_t svb0 = (uint32_t)__cvta_generic_to_shared(&sV[0][0]);
    const uint32_t svb1 = (uint32_t)__cvta_generic_to_shared(&sV[1][0]);

    const int mid = lane >> 3, mrow = lane & 7;
    const int lmoff = ((mid & 1) * 8 + mrow) * PITCH + (mid >> 1) * 16;

    auto stage = [&](int c, int s) {
        const char* hsrc = (const char*)(g_hb + ((size_t)(bN + c * KC) << 6));
        const int row = t >> 1, seg = t & 1;
        const uint32_t d = (s ? shb1 : shb0) + row * PITCH + seg * 64;
        const char* gp = hsrc + row * 128 + seg * 64;
        CP16(d,      gp);
        CP16(d + 16, gp + 16);
        CP16(d + 32, gp + 32);
        CP16(d + 48, gp + 48);
        if (t < 16) {
            CP16((s ? stb1 : stb0) + t * 16, (const char*)(g_t + bN + c * KC) + t * 16);
        } else if (t < 32) {
            CP16((s ? svb1 : svb0) + (t - 16) * 16, (const char*)(g_v + bN + c * KC) + (t - 16) * 16);
        }
    };

    // mask loads for one 16-j step: jglob = c*KC + kt*16
    auto ldmask = [&](int jglob, int2* m) {
        const int off_lo = jglob + 2 * tq, off_hi = off_lo + 8;
        m[0] = *(const int2*)(pa0 + off_lo); m[1] = *(const int2*)(pa0 + off_hi);
        m[2] = *(const int2*)(pa1 + off_lo); m[3] = *(const int2*)(pa1 + off_hi);
        m[4] = *(const int2*)(pj0 + off_lo); m[5] = *(const int2*)(pj0 + off_hi);
        m[6] = *(const int2*)(pj1 + off_lo); m[7] = *(const int2*)(pj1 + off_hi);
    };

    float accA[32], accJ[32];
    #pragma unroll
    for (int q = 0; q < 32; ++q) { accA[q] = 0.f; accJ[q] = 0.f; }
    float denA0 = 0.f, denA1 = 0.f, denJ0 = 0.f, denJ1 = 0.f;

    const int c0 = sp * CPS;
    stage(c0, 0);
    CP_COMMIT();

    int2 curm[8], nxtm[8];
    ldmask(c0 * KC, curm);

    for (int ci = 0; ci < CPS; ++ci) {
        const int c = c0 + ci;
        const int s = ci & 1;
        CP_WAIT0();
        __syncthreads();
        if (ci + 1 < CPS) { stage(c + 1, 1 - s); CP_COMMIT(); }

        const uint32_t hbase = (s ? shb1 : shb0) + lmoff;
        const float* sTs = sT[s];
        const float* sVs = sV[s];

        #pragma unroll
        for (int kt = 0; kt < 4; ++kt) {
            // prefetch next step's masks (deep MLP)
            if (kt < 3)            ldmask(c * KC + (kt + 1) * 16, nxtm);
            else if (ci + 1 < CPS) ldmask((c + 1) * KC, nxtm);

            const int jl = kt * 16;
            const float2 tlo = *(const float2*)&sTs[jl + 2 * tq];
            const float2 thi = *(const float2*)&sTs[jl + 2 * tq + 8];
            const float2 vlo = *(const float2*)&sVs[jl + 2 * tq];
            const float2 vhi = *(const float2*)&sVs[jl + 2 * tq + 8];

            const float pv00 = pvsel(si0 * tlo.x, ui0 * vlo.x);
            const float pv01 = pvsel(si0 * tlo.y, ui0 * vlo.y);
            const float pv0h0 = pvsel(si0 * thi.x, ui0 * vhi.x);
            const float pv0h1 = pvsel(si0 * thi.y, ui0 * vhi.y);
            const float pv10 = pvsel(si1 * tlo.x, ui1 * vlo.x);
            const float pv11 = pvsel(si1 * tlo.y, ui1 * vlo.y);
            const float pv1h0 = pvsel(si1 * thi.x, ui1 * vhi.x);
            const float pv1h1 = pvsel(si1 * thi.y, ui1 * vhi.y);

            const float A00 = curm[0].x ? pv00 : 0.f,  A01 = curm[0].y ? pv01 : 0.f;
            const float A0h0 = curm[1].x ? pv0h0 : 0.f, A0h1 = curm[1].y ? pv0h1 : 0.f;
            const float A10 = curm[2].x ? pv10 : 0.f,  A11 = curm[2].y ? pv11 : 0.f;
            const float A1h0 = curm[3].x ? pv1h0 : 0.f, A1h1 = curm[3].y ? pv1h1 : 0.f;
            const float J00 = curm[4].x ? pv00 : 0.f,  J01 = curm[4].y ? pv01 : 0.f;
            const float J0h0 = curm[5].x ? pv0h0 : 0.f, J0h1 = curm[5].y ? pv0h1 : 0.f;
            const float J10 = curm[6].x ? pv10 : 0.f,  J11 = curm[6].y ? pv11 : 0.f;
            const float J1h0 = curm[7].x ? pv1h0 : 0.f, J1h1 = curm[7].y ? pv1h1 : 0.f;

            denA0 += (A00 + A01) + (A0h0 + A0h1);
            denA1 += (A10 + A11) + (A1h0 + A1h1);
            denJ0 += (J00 + J01) + (J0h0 + J0h1);
            denJ1 += (J10 + J11) + (J1h0 + J1h1);

            const uint32_t aA0 = packbf(A00, A01),   aA1 = packbf(A10, A11);
            const uint32_t aA2 = packbf(A0h0, A0h1), aA3 = packbf(A1h0, A1h1);
            const uint32_t aJ0 = packbf(J00, J01),   aJ1 = packbf(J10, J11);
            const uint32_t aJ2 = packbf(J0h0, J0h1), aJ3 = packbf(J1h0, J1h1);

            const uint32_t hb = hbase + kt * (16 * PITCH);
            #pragma unroll
            for (int np = 0; np < 4; ++np) {
                uint32_t b0, b1, b2, b3;
                ldsm4t(b0, b1, b2, b3, hb + np * 32);
                mma_bf16(&accA[(2 * np) * 4],     aA0, aA1, aA2, aA3, b0, b1);
                mma_bf16(&accA[(2 * np + 1) * 4], aA0, aA1, aA2, aA3, b2, b3);
                mma_bf16(&accJ[(2 * np) * 4],     aJ0, aJ1, aJ2, aJ3, b0, b1);
                mma_bf16(&accJ[(2 * np + 1) * 4], aJ0, aJ1, aJ2, aJ3, b2, b3);
            }
            #pragma unroll
            for (int q = 0; q < 8; ++q) curm[q] = nxtm[q];
        }
    }

    // denominator butterfly over the 4 lanes sharing g
    denA0 += __shfl_xor_sync(0xffffffffu, denA0, 1);
    denA0 += __shfl_xor_sync(0xffffffffu, denA0, 2);
    denA1 += __shfl_xor_sync(0xffffffffu, denA1, 1);
    denA1 += __shfl_xor_sync(0xffffffffu, denA1, 2);
    denJ0 += __shfl_xor_sync(0xffffffffu, denJ0, 1);
    denJ0 += __shfl_xor_sync(0xffffffffu, denJ0, 2);
    denJ1 += __shfl_xor_sync(0xffffffffu, denJ1, 1);
    denJ1 += __shfl_xor_sync(0xffffffffu, denJ1, 2);

    // write partials
    float* nA = g_nA[sp];
    float* nJ = g_nJ[sp];
    const size_t o0b = (size_t)(bN + i_base + r0) << 6;
    const size_t o1b = (size_t)(bN + i_base + r1) << 6;
    #pragma unroll
    for (int n = 0; n < 8; ++n) {
        const int cc = n * 8 + 2 * tq;
        *(float2*)(nA + o0b + cc) = make_float2(accA[n * 4 + 0], accA[n * 4 + 1]);
        *(float2*)(nA + o1b + cc) = make_float2(accA[n * 4 + 2], accA[n * 4 + 3]);
        *(float2*)(nJ + o0b + cc) = make_float2(accJ[n * 4 + 0], accJ[n * 4 + 1]);
        *(float2*)(nJ + o1b + cc) = make_float2(accJ[n * 4 + 2], accJ[n * 4 + 3]);
    }
    if (tq == 0) {
        g_dA[sp][bN + i_base + r0] = denA0;
        g_dA[sp][bN + i_base + r1] = denA1;
        g_dJ[sp][bN + i_base + r0] = denJ0;
        g_dJ[sp][bN + i_base + r1] = denJ1;
    }
}

// =====================================================================
// Kernel C: combine splits, normalize, blend, residual
// =====================================================================
__global__ __launch_bounds__(256) void combine_kernel(
    const float* __restrict__ feats, float* __restrict__ out)
{
    const int idx = (blockIdx.x * blockDim.x + threadIdx.x) * 4;
    const int n = idx >> 6;
    const int d = idx & 63;

    float4 na = make_float4(0.f, 0.f, 0.f, 0.f);
    float4 nj = make_float4(0.f, 0.f, 0.f, 0.f);
    float da = 0.f, dj = 0.f;
    #pragma unroll
    for (int sp = 0; sp < SPLIT; ++sp) {
        const float4 a = *(const float4*)(g_nA[sp] + idx);
        const float4 j = *(const float4*)(g_nJ[sp] + idx);
        na.x += a.x; na.y += a.y; na.z += a.z; na.w += a.w;
        nj.x += j.x; nj.y += j.y; nj.z += j.z; nj.w += j.w;
        da += g_dA[sp][n];
        dj += g_dJ[sp][n];
    }
    const float ra = 1.0f / da;
    const float rj = 1.0f / dj;
    const float4 lA = *(const float4*)&g_lam[d];
    const float4 lJ = *(const float4*)&g_lam[DD + d];
    const float4 f = *(const float4*)(feats + idx);
    float4 o;
    o.x = lA.x * na.x * ra + lJ.x * nj.x * rj + f.x;
    o.y = lA.y * na.y * ra + lJ.y * nj.y * rj + f.y;
    o.z = lA.z * na.z * ra + lJ.z * nj.z * rj + f.z;
    o.w = lA.w * na.w * ra + lJ.w * nj.w * rj + f.w;
    *(float4*)(out + idx) = o;
}

extern "C" void kernel_launch(void* const* d_in, const int* in_sizes, int n_in,
                              void* d_out, int out_size) {
    (void)in_sizes; (void)n_in; (void)out_size;
    const int*   mask_adj      = (const int*)d_in[0];
    const int*   mask_job      = (const int*)d_in[1];
    const int*   bidx          = (const int*)d_in[2];
    const float* feats         = (const float*)d_in[3];
    const float* W             = (const float*)d_in[4];
    const float* attn_src      = (const float*)d_in[5];
    const float* attn_dst      = (const float*)d_in[6];
    const float* lambda_params = (const float*)d_in[7];
    float* out = (float*)d_out;

    prep_kernel<<<BB * NN / 16, 512>>>(feats, W, attn_src, attn_dst, lambda_params);
    attn_hmma_kernel<<<dim3(NN / TIM, BB, SPLIT), 128>>>(mask_adj, mask_job, bidx);
    combine_kernel<<<BB * NN * DD / 4 / 256, 256>>>(feats, out);
}